// round 11
// baseline (speedup 1.0000x reference)
#include <cuda_runtime.h>
#include <cuda_fp16.h>
#include <stdint.h>
#include <math.h>

// Problem constants: B=4, T=2048, E=1024, H*D=1024
#define BBATCH 4
#define TSEQ   2048
#define EDIM   1024
#define MTOK   (BBATCH * TSEQ)

// ---------------------------------------------------------------------------
// Scratch (device globals, zero-initialized at module load)
// ---------------------------------------------------------------------------
__device__ __half g_xh [MTOK * EDIM];
__device__ __half g_xl [MTOK * EDIM];
__device__ __half g_wjh[EDIM * EDIM];
__device__ __half g_wjl[EDIM * EDIM];
__device__ __half g_woh[EDIM * EDIM];
__device__ __half g_wol[EDIM * EDIM];
__device__ __half g_wvth[EDIM * EDIM];
__device__ __half g_wvtl[EDIM * EDIM];
__device__ __half g_Wch[EDIM * EDIM];
__device__ __half g_Wcl[EDIM * EDIM];
__device__ __half g_uh [EDIM * MTOK];           // u^T hi only
__device__ float g_scpart[8 * MTOK];
__device__ float g_sc  [MTOK];
__device__ float g_cmax[MTOK];
__device__ float g_chunkmax[BBATCH * 32];

// ---------------------------------------------------------------------------
// helpers
// ---------------------------------------------------------------------------
__device__ __forceinline__ uint32_t smem_u32(const void* p) {
    uint32_t a;
    asm("{ .reg .u64 t; cvta.to.shared.u64 t, %1; cvt.u32.u64 %0, t; }"
        : "=r"(a) : "l"(p));
    return a;
}
__device__ __forceinline__ uint32_t SWZ(uint32_t x) { return x ^ ((x >> 3) & 0x70); }

__device__ __forceinline__ void cp16(uint32_t dst, const void* src) {
    asm volatile("cp.async.cg.shared.global [%0], [%1], 16;" :: "r"(dst), "l"(src) : "memory");
}
#define CP_COMMIT() asm volatile("cp.async.commit_group;" ::: "memory")
#define CP_WAIT1()  asm volatile("cp.async.wait_group 1;" ::: "memory")

__device__ __forceinline__ void ldm_x4(uint32_t* r, uint32_t addr) {
    asm volatile("ldmatrix.sync.aligned.m8n8.x4.shared.b16 {%0,%1,%2,%3}, [%4];"
                 : "=r"(r[0]), "=r"(r[1]), "=r"(r[2]), "=r"(r[3]) : "r"(addr));
}
__device__ __forceinline__ void mma16816(float* d, const uint32_t* a, const uint32_t* b) {
    asm volatile(
        "mma.sync.aligned.m16n8k16.row.col.f32.f16.f16.f32 "
        "{%0,%1,%2,%3}, {%4,%5,%6,%7}, {%8,%9}, {%0,%1,%2,%3};"
        : "+f"(d[0]), "+f"(d[1]), "+f"(d[2]), "+f"(d[3])
        : "r"(a[0]), "r"(a[1]), "r"(a[2]), "r"(a[3]), "r"(b[0]), "r"(b[1]));
}
__device__ __forceinline__ uint32_t packh(float a, float b) {
    __half2 h = __floats2half2_rn(a, b);
    return *(uint32_t*)&h;
}

// ---------------------------------------------------------------------------
// NT tensor-core GEMM (mma.sync fp16, fp32 accum), NSEG K-segment products:
//   C[m,n] = sum_s A_s[m,:] . B_s[n,:]
// CTA tile 128x128, K chunks of 64, 3-stage cp.async pipeline.
// EPI 0: row sum-of-squares -> scpart[bx*MTOK + row]
// EPI 1: fp16 hi/lo split store (Ohi/Olo), leading dim ldo
// EPI 2: fp16 hi-only store (Ohi), leading dim ldo
// ---------------------------------------------------------------------------
#define STAGE 32768
#define SMEM_BYTES (3 * STAGE)

template <int EPI, int NSEG>
__global__ __launch_bounds__(256) void tc_gemm(
    const __half* __restrict__ A0, const __half* __restrict__ A1,
    const __half* __restrict__ A2,
    const __half* __restrict__ B0, const __half* __restrict__ B1,
    const __half* __restrict__ B2,
    int lda, int ldb, int Kseg,
    float* __restrict__ scpart,
    __half* __restrict__ Ohi, __half* __restrict__ Olo, int ldo)
{
    extern __shared__ __align__(1024) char dsm[];
    const uint32_t sbase = smem_u32(dsm);
    const int tid  = threadIdx.x;
    const int lane = tid & 31;
    const int wid  = tid >> 5;
    const int warp_m = wid & 1;
    const int warp_n = wid >> 1;
    const int m0 = blockIdx.y * 128;
    const int n0 = blockIdx.x * 128;

    const __half* Aarr[3] = {A0, A1, A2};
    const __half* Barr[3] = {B0, B1, B2};

    const int nch = Kseg >> 6;
    const int n   = NSEG * nch;

    float acc[4][4][4];
#pragma unroll
    for (int a = 0; a < 4; ++a)
#pragma unroll
        for (int b = 0; b < 4; ++b)
#pragma unroll
            for (int c = 0; c < 4; ++c) acc[a][b][c] = 0.f;

    auto load_chunk = [&](int j) {
        const int st  = j % 3;
        const int seg = j / nch;
        const int kc  = (j - seg * nch) << 6;
        const uint32_t sA = sbase + st * STAGE;
        const __half* As = Aarr[seg];
        const __half* Bs = Barr[seg];
#pragma unroll
        for (int i = 0; i < 4; ++i) {
            int id = i * 256 + tid;
            int row = id >> 3, ch = id & 7;
            cp16(sA + SWZ(row * 128 + ch * 16),
                 As + (size_t)(m0 + row) * lda + kc + ch * 8);
        }
#pragma unroll
        for (int i = 0; i < 4; ++i) {
            int id = i * 256 + tid;
            int row = id >> 3, ch = id & 7;
            cp16(sA + 16384 + SWZ(row * 128 + ch * 16),
                 Bs + (size_t)(n0 + row) * ldb + kc + ch * 8);
        }
    };

    const int arow = warp_m * 64 + (lane & 15);
    const int asel = lane >> 4;
    const int brow = warp_n * 32 + ((lane >> 4) << 3) + (lane & 7);
    const int bsel = (lane >> 3) & 1;

    load_chunk(0); CP_COMMIT();
    load_chunk(1); CP_COMMIT();

    for (int j = 0; j < n; ++j) {
        CP_WAIT1();
        __syncthreads();
        if (j + 2 < n) load_chunk(j + 2);
        CP_COMMIT();

        const uint32_t sA = sbase + (j % 3) * STAGE;
        const uint32_t sB = sA + 16384;
#pragma unroll
        for (int ks = 0; ks < 4; ++ks) {
            uint32_t afr[4][4], bfr[2][4];
#pragma unroll
            for (int mt = 0; mt < 4; ++mt)
                ldm_x4(afr[mt], sA + SWZ((arow + mt * 16) * 128 + (ks * 2 + asel) * 16));
#pragma unroll
            for (int p = 0; p < 2; ++p)
                ldm_x4(bfr[p], sB + SWZ((brow + p * 16) * 128 + (ks * 2 + bsel) * 16));
#pragma unroll
            for (int mt = 0; mt < 4; ++mt)
#pragma unroll
                for (int nt = 0; nt < 4; ++nt)
                    mma16816(acc[mt][nt], afr[mt], &bfr[nt >> 1][(nt & 1) * 2]);
        }
    }
    __syncthreads();

    const int rbase = warp_m * 64 + (lane >> 2);
    const int cbase = warp_n * 32 + (lane & 3) * 2;

    if (EPI == 0) {
        float* red = (float*)dsm;
#pragma unroll
        for (int mt = 0; mt < 4; ++mt) {
#pragma unroll
            for (int h = 0; h < 2; ++h) {
                float s = 0.f;
#pragma unroll
                for (int nt = 0; nt < 4; ++nt) {
                    float d0 = acc[mt][nt][2 * h], d1 = acc[mt][nt][2 * h + 1];
                    s = fmaf(d0, d0, fmaf(d1, d1, s));
                }
                s += __shfl_xor_sync(0xffffffffu, s, 1);
                s += __shfl_xor_sync(0xffffffffu, s, 2);
                if ((lane & 3) == 0)
                    red[warp_n * 128 + warp_m * 64 + mt * 16 + h * 8 + (lane >> 2)] = s;
            }
        }
        __syncthreads();
        if (tid < 128) {
            float s = red[tid] + red[128 + tid] + red[256 + tid] + red[384 + tid];
            scpart[(size_t)blockIdx.x * MTOK + m0 + tid] = s;
        }
    } else if (EPI == 1) {
#pragma unroll
        for (int mt = 0; mt < 4; ++mt)
#pragma unroll
            for (int h = 0; h < 2; ++h) {
                int row = m0 + rbase + mt * 16 + h * 8;
#pragma unroll
                for (int nt = 0; nt < 4; ++nt) {
                    float v0 = acc[mt][nt][2 * h], v1 = acc[mt][nt][2 * h + 1];
                    __half h0 = __float2half_rn(v0);
                    __half h1 = __float2half_rn(v1);
                    uint32_t hp = packh(v0, v1);
                    uint32_t lp = packh(v0 - __half2float(h0), v1 - __half2float(h1));
                    size_t off = (size_t)row * ldo + n0 + cbase + nt * 8;
                    *(uint32_t*)(Ohi + off) = hp;
                    *(uint32_t*)(Olo + off) = lp;
                }
            }
    } else {
#pragma unroll
        for (int mt = 0; mt < 4; ++mt)
#pragma unroll
            for (int h = 0; h < 2; ++h) {
                int row = m0 + rbase + mt * 16 + h * 8;
#pragma unroll
                for (int nt = 0; nt < 4; ++nt) {
                    uint32_t hp = packh(acc[mt][nt][2 * h], acc[mt][nt][2 * h + 1]);
                    *(uint32_t*)(Ohi + (size_t)row * ldo + n0 + cbase + nt * 8) = hp;
                }
            }
    }
}

// ---------------------------------------------------------------------------
// Fused causal attention: out[t,e] = (1/Z_t) * sum_{s<=t} exp(st*ss - m_t) u[s,e]
// A (P hi/lo fp16 fragments) generated in registers; B = uh tiles via cp.async.
// Chunk skipping: skip 64-wide s-chunk if stmin*(chunkmax - cmin) < -20
// (valid upper bound: cmax_t >= cmin and st >= stmin > 0).
// ---------------------------------------------------------------------------
#define AT_STAGE 16384
#define AT_SC    (3 * AT_STAGE)               // sc_all float[2048]
#define AT_MROW  (AT_SC + 8192)               // mrow float[128]
#define AT_ZROW  (AT_MROW + 512)              // zrow float[128]
#define AT_KEEP  (AT_ZROW + 512)              // keepList int[32]
#define AT_META  (AT_KEEP + 128)              // [0]=keepCount
#define AT_SMEM  (AT_META + 16)

__global__ __launch_bounds__(256) void attn_fused(
    const __half* __restrict__ uh, float* __restrict__ out)
{
    extern __shared__ __align__(1024) char dsm[];
    const uint32_t sbase = smem_u32(dsm);
    float* sc_all = (float*)(dsm + AT_SC);
    float* mrow   = (float*)(dsm + AT_MROW);
    float* zrow   = (float*)(dsm + AT_ZROW);
    int*   keepL  = (int*)(dsm + AT_KEEP);
    int*   meta   = (int*)(dsm + AT_META);

    const int tid  = threadIdx.x;
    const int lane = tid & 31;
    const int wid  = tid >> 5;
    const int warp_m = wid & 1;
    const int warp_n = wid >> 1;
    const int m0 = blockIdx.y * 128;        // token tile (within batch)
    const int n0 = blockIdx.x * 128;        // e tile
    const int z  = blockIdx.z;

    for (int i = tid * 4; i < TSEQ; i += 1024)
        *(float4*)&sc_all[i] = *(const float4*)&g_sc[z * TSEQ + i];
    __syncthreads();
    if (tid < 128)
        mrow[tid] = sc_all[m0 + tid] * g_cmax[z * TSEQ + m0 + tid];

    if (wid == 0) {
        float v = fminf(fminf(sc_all[m0 + lane * 4], sc_all[m0 + lane * 4 + 1]),
                        fminf(sc_all[m0 + lane * 4 + 2], sc_all[m0 + lane * 4 + 3]));
#pragma unroll
        for (int o = 16; o; o >>= 1) v = fminf(v, __shfl_xor_sync(0xffffffffu, v, o));
        float stmin = v;
        float cmin = g_cmax[z * TSEQ + m0];
        int nch = (m0 + 128) >> 6;
        bool keep = false;
        if (lane < nch) {
            float chm = g_chunkmax[z * 32 + lane];
            keep = stmin * (chm - cmin) > -20.f;
        }
        uint32_t mask = __ballot_sync(0xffffffffu, keep);
        if (keep) keepL[__popc(mask & ((1u << lane) - 1))] = lane;
        if (lane == 0) meta[0] = __popc(mask);
    }
    __syncthreads();
    const int n = meta[0];

    const int g  = lane >> 2;
    const int tc = (lane & 3) * 2;
    float stR[8], mR[8];
    int   trow[8];
#pragma unroll
    for (int mt = 0; mt < 4; ++mt)
#pragma unroll
        for (int h = 0; h < 2; ++h) {
            int l = warp_m * 64 + mt * 16 + h * 8 + g;
            trow[mt * 2 + h] = m0 + l;
            stR[mt * 2 + h] = sc_all[m0 + l];
            mR[mt * 2 + h]  = mrow[l];
        }
    float zacc[8];
#pragma unroll
    for (int i = 0; i < 8; ++i) zacc[i] = 0.f;

    float acc[4][4][4];
#pragma unroll
    for (int a = 0; a < 4; ++a)
#pragma unroll
        for (int b = 0; b < 4; ++b)
#pragma unroll
            for (int c = 0; c < 4; ++c) acc[a][b][c] = 0.f;

    auto load_chunk = [&](int j) {
        const int c = keepL[j];
        const uint32_t sA = sbase + (j % 3) * AT_STAGE;
#pragma unroll
        for (int i = 0; i < 4; ++i) {
            int id = i * 256 + tid;
            int row = id >> 3, ch = id & 7;
            cp16(sA + SWZ(row * 128 + ch * 16),
                 uh + (size_t)(n0 + row) * MTOK + z * TSEQ + c * 64 + ch * 8);
        }
    };

    const int brow = warp_n * 32 + ((lane >> 4) << 3) + (lane & 7);
    const int bsel = (lane >> 3) & 1;

    load_chunk(0); CP_COMMIT();
    if (n > 1) load_chunk(1);
    CP_COMMIT();

    for (int j = 0; j < n; ++j) {
        CP_WAIT1();
        __syncthreads();
        if (j + 2 < n) load_chunk(j + 2);
        CP_COMMIT();

        const int c = keepL[j];
        const int sb = c * 64;
        const uint32_t sB = sbase + (j % 3) * AT_STAGE;
#pragma unroll
        for (int ks = 0; ks < 4; ++ks) {
            uint32_t bfr[2][4];
#pragma unroll
            for (int p = 0; p < 2; ++p)
                ldm_x4(bfr[p], sB + SWZ((brow + p * 16) * 128 + (ks * 2 + bsel) * 16));

            const int s0 = sb + ks * 16 + tc;
            const float ss0 = sc_all[s0],     ss1 = sc_all[s0 + 1];
            const float ss2 = sc_all[s0 + 8], ss3 = sc_all[s0 + 9];

            uint32_t ah[4][4], al[4][4];
#pragma unroll
            for (int mt = 0; mt < 4; ++mt) {
#pragma unroll
                for (int h = 0; h < 2; ++h) {
                    const int r = mt * 2 + h;
                    const int t = trow[r];
                    const float st = stR[r], m = mR[r];
                    float p0 = (s0     <= t) ? __expf(fmaf(st, ss0, -m)) : 0.f;
                    float p1 = (s0 + 1 <= t) ? __expf(fmaf(st, ss1, -m)) : 0.f;
                    float p2 = (s0 + 8 <= t) ? __expf(fmaf(st, ss2, -m)) : 0.f;
                    float p3 = (s0 + 9 <= t) ? __expf(fmaf(st, ss3, -m)) : 0.f;
                    zacc[r] += (p0 + p1) + (p2 + p3);
                    __half h0 = __float2half_rn(p0), h1 = __float2half_rn(p1);
                    __half h2 = __float2half_rn(p2), h3 = __float2half_rn(p3);
                    ah[mt][h]     = packh(p0, p1);
                    ah[mt][h + 2] = packh(p2, p3);
                    al[mt][h]     = packh(p0 - __half2float(h0), p1 - __half2float(h1));
                    al[mt][h + 2] = packh(p2 - __half2float(h2), p3 - __half2float(h3));
                }
            }
#pragma unroll
            for (int mt = 0; mt < 4; ++mt)
#pragma unroll
                for (int nt = 0; nt < 4; ++nt) {
                    mma16816(acc[mt][nt], ah[mt], &bfr[nt >> 1][(nt & 1) * 2]);
                    mma16816(acc[mt][nt], al[mt], &bfr[nt >> 1][(nt & 1) * 2]);
                }
        }
    }

    // Z reduce (warp_n == 0 warps cover all 128 rows)
    if (warp_n == 0) {
#pragma unroll
        for (int r = 0; r < 8; ++r) {
            float v = zacc[r];
            v += __shfl_xor_sync(0xffffffffu, v, 1);
            v += __shfl_xor_sync(0xffffffffu, v, 2);
            if ((lane & 3) == 0)
                zrow[warp_m * 64 + (r >> 1) * 16 + (r & 1) * 8 + g] = v;
        }
    }
    __syncthreads();

    const int rbase = warp_m * 64 + (lane >> 2);
    const int cbase = warp_n * 32 + (lane & 3) * 2;
#pragma unroll
    for (int mt = 0; mt < 4; ++mt)
#pragma unroll
        for (int h = 0; h < 2; ++h) {
            int rl = rbase + mt * 16 + h * 8;
            float scale = 1.f / zrow[rl];
            float* Cp = out + (size_t)z * TSEQ * EDIM + (size_t)(m0 + rl) * EDIM + n0 + cbase;
#pragma unroll
            for (int nt = 0; nt < 4; ++nt) {
                float2 v = make_float2(acc[mt][nt][2 * h] * scale,
                                       acc[mt][nt][2 * h + 1] * scale);
                *(float2*)(Cp + nt * 8) = v;
            }
        }
}

// ---------------------------------------------------------------------------
// fp32 -> fp16 hi/lo split
// ---------------------------------------------------------------------------
__global__ __launch_bounds__(256) void split_kernel(
    const float* __restrict__ src, __half* __restrict__ hi,
    __half* __restrict__ lo, int nElem)
{
    int i = (blockIdx.x * 256 + threadIdx.x) * 4;
    if (i >= nElem) return;
    float4 v = *(const float4*)(src + i);
    __half h0 = __float2half_rn(v.x), h1 = __float2half_rn(v.y);
    __half h2 = __float2half_rn(v.z), h3 = __float2half_rn(v.w);
    *(uint32_t*)(hi + i)     = packh(v.x, v.y);
    *(uint32_t*)(hi + i + 2) = packh(v.z, v.w);
    *(uint32_t*)(lo + i)     = packh(v.x - __half2float(h0), v.y - __half2float(h1));
    *(uint32_t*)(lo + i + 2) = packh(v.z - __half2float(h2), v.w - __half2float(h3));
}

// transpose + split (1024 x 1024)
__global__ __launch_bounds__(256) void transpose_split_kernel(
    const float* __restrict__ src, __half* __restrict__ th, __half* __restrict__ tl)
{
    __shared__ float tile[32][33];
    int x = blockIdx.x * 32 + threadIdx.x;
    int y0 = blockIdx.y * 32 + threadIdx.y;
#pragma unroll
    for (int i = 0; i < 4; ++i)
        tile[threadIdx.y + i * 8][threadIdx.x] = src[(size_t)(y0 + i * 8) * EDIM + x];
    __syncthreads();
    int ox = blockIdx.y * 32 + threadIdx.x;
    int oy0 = blockIdx.x * 32 + threadIdx.y;
#pragma unroll
    for (int i = 0; i < 4; ++i) {
        float v = tile[threadIdx.x][threadIdx.y + i * 8];
        __half h = __float2half_rn(v);
        th[(size_t)(oy0 + i * 8) * EDIM + ox] = h;
        tl[(size_t)(oy0 + i * 8) * EDIM + ox] = __float2half_rn(v - __half2float(h));
    }
}

// ---------------------------------------------------------------------------
// per-batch scalar kernel: sc reduce, chunk maxes, inclusive cummax
// ---------------------------------------------------------------------------
__global__ __launch_bounds__(1024) void scalar_kernel()
{
    __shared__ float s[TSEQ];
    const int b = blockIdx.x, tid = threadIdx.x;
#pragma unroll
    for (int h = 0; h < 2; ++h) {
        int t = tid + h * 1024;
        float v = 0.f;
#pragma unroll
        for (int p = 0; p < 8; ++p) v += g_scpart[p * MTOK + b * TSEQ + t];
        v *= 0.03125f;
        s[t] = v;
        g_sc[b * TSEQ + t] = v;
    }
    __syncthreads();
    if (tid < 32) {
        float m = s[tid * 64];
        for (int i = 1; i < 64; ++i) m = fmaxf(m, s[tid * 64 + i]);
        g_chunkmax[b * 32 + tid] = m;
    }
    // inclusive max-scan
    for (int off = 1; off < TSEQ; off <<= 1) {
        float v0 = s[tid];
        if (tid >= off) v0 = fmaxf(v0, s[tid - off]);
        float v1 = fmaxf(s[tid + 1024], s[tid + 1024 - off]);
        __syncthreads();
        s[tid] = v0; s[tid + 1024] = v1;
        __syncthreads();
    }
    g_cmax[b * TSEQ + tid]        = s[tid];
    g_cmax[b * TSEQ + tid + 1024] = s[tid + 1024];
}

// ---------------------------------------------------------------------------
// launch
// ---------------------------------------------------------------------------
extern "C" void kernel_launch(void* const* d_in, const int* in_sizes, int n_in,
                              void* d_out, int out_size)
{
    const float* x   = (const float*)d_in[0];
    const float* wj  = (const float*)d_in[1];
    const float* wjv = (const float*)d_in[2];
    const float* wo  = (const float*)d_in[3];
    float* out = (float*)d_out;

    __half *xh, *xl, *wjh, *wjl, *woh, *wol, *wvth, *wvtl, *Wch, *Wcl, *uh;
    float *scpart;
    cudaGetSymbolAddress((void**)&xh, g_xh);   cudaGetSymbolAddress((void**)&xl, g_xl);
    cudaGetSymbolAddress((void**)&wjh, g_wjh); cudaGetSymbolAddress((void**)&wjl, g_wjl);
    cudaGetSymbolAddress((void**)&woh, g_woh); cudaGetSymbolAddress((void**)&wol, g_wol);
    cudaGetSymbolAddress((void**)&wvth, g_wvth); cudaGetSymbolAddress((void**)&wvtl, g_wvtl);
    cudaGetSymbolAddress((void**)&Wch, g_Wch); cudaGetSymbolAddress((void**)&Wcl, g_Wcl);
    cudaGetSymbolAddress((void**)&uh, g_uh);
    cudaGetSymbolAddress((void**)&scpart, g_scpart);

    cudaFuncSetAttribute(tc_gemm<0, 3>, cudaFuncAttributeMaxDynamicSharedMemorySize, SMEM_BYTES);
    cudaFuncSetAttribute(tc_gemm<1, 3>, cudaFuncAttributeMaxDynamicSharedMemorySize, SMEM_BYTES);
    cudaFuncSetAttribute(tc_gemm<2, 2>, cudaFuncAttributeMaxDynamicSharedMemorySize, SMEM_BYTES);
    cudaFuncSetAttribute(attn_fused, cudaFuncAttributeMaxDynamicSharedMemorySize, AT_SMEM);

    // 1. splits
    split_kernel<<<MTOK * EDIM / 1024, 256>>>(x, xh, xl, MTOK * EDIM);
    split_kernel<<<EDIM * EDIM / 1024, 256>>>(wj, wjh, wjl, EDIM * EDIM);
    split_kernel<<<EDIM * EDIM / 1024, 256>>>(wo, woh, wol, EDIM * EDIM);
    transpose_split_kernel<<<dim3(32, 32), dim3(32, 8)>>>(wjv, wvth, wvtl);

    // 2. sc partials: ||x@wj^T||^2  (hi*hi + hi*lo + lo*hi)
    tc_gemm<0, 3><<<dim3(8, 64), 256, SMEM_BYTES>>>(
        xh, xh, xl, wjh, wjl, wjh, EDIM, EDIM, EDIM,
        scpart, nullptr, nullptr, 0);
    scalar_kernel<<<BBATCH, 1024>>>();

    // 3. Wc = wo @ wjv  (hi*hi + hi*lo + lo*hi)  -- corrected segment pairing
    tc_gemm<1, 3><<<dim3(8, 8), 256, SMEM_BYTES>>>(
        woh, woh, wol, wvth, wvtl, wvth, EDIM, EDIM, EDIM,
        nullptr, Wch, Wcl, EDIM);

    // 4. u^T = Wc @ x^T (2-product: (Wch+Wcl)·xh) -> hi only
    tc_gemm<2, 2><<<dim3(64, 8), 256, SMEM_BYTES>>>(
        Wch, Wcl, nullptr, xh, xh, nullptr, EDIM, EDIM, EDIM,
        nullptr, uh, nullptr, MTOK);

    // 5. fused causal attention with in-register P and chunk skipping
    attn_fused<<<dim3(8, 16, BBATCH), 256, AT_SMEM>>>(uh, out);
}

// round 12
// speedup vs baseline: 1.3850x; 1.3850x over previous
#include <cuda_runtime.h>
#include <cuda_fp16.h>
#include <stdint.h>
#include <math.h>

// Problem constants: B=4, T=2048, E=1024, H*D=1024
#define BBATCH 4
#define TSEQ   2048
#define EDIM   1024
#define MTOK   (BBATCH * TSEQ)

// ---------------------------------------------------------------------------
// Scratch (device globals, zero-initialized at module load)
// ---------------------------------------------------------------------------
__device__ __half g_xh [MTOK * EDIM];
__device__ __half g_xl [MTOK * EDIM];
__device__ __half g_wjh[EDIM * EDIM];
__device__ __half g_wjl[EDIM * EDIM];
__device__ __half g_woh[EDIM * EDIM];
__device__ __half g_wol[EDIM * EDIM];
__device__ __half g_wvth[EDIM * EDIM];
__device__ __half g_wvtl[EDIM * EDIM];
__device__ __half g_Wch[EDIM * EDIM];
__device__ __half g_Wcl[EDIM * EDIM];
__device__ __half g_uh [EDIM * MTOK];                    // u^T hi only
__device__ __half g_Ph [(size_t)BBATCH * TSEQ * TSEQ];   // P hi (16MB)
__device__ __half g_Pl [(size_t)BBATCH * TSEQ * TSEQ];   // P lo (16MB)
__device__ float g_scpart[8 * MTOK];
__device__ float g_sc  [MTOK];
__device__ float g_cmax[MTOK];
__device__ float g_Z   [MTOK];
__device__ float g_chunkmax[BBATCH * 32];

// ---------------------------------------------------------------------------
// helpers
// ---------------------------------------------------------------------------
__device__ __forceinline__ uint32_t smem_u32(const void* p) {
    uint32_t a;
    asm("{ .reg .u64 t; cvta.to.shared.u64 t, %1; cvt.u32.u64 %0, t; }"
        : "=r"(a) : "l"(p));
    return a;
}
__device__ __forceinline__ uint32_t SWZ(uint32_t x) { return x ^ ((x >> 3) & 0x70); }

__device__ __forceinline__ void cp16(uint32_t dst, const void* src) {
    asm volatile("cp.async.cg.shared.global [%0], [%1], 16;" :: "r"(dst), "l"(src) : "memory");
}
#define CP_COMMIT() asm volatile("cp.async.commit_group;" ::: "memory")
#define CP_WAIT1()  asm volatile("cp.async.wait_group 1;" ::: "memory")

__device__ __forceinline__ void ldm_x4(uint32_t* r, uint32_t addr) {
    asm volatile("ldmatrix.sync.aligned.m8n8.x4.shared.b16 {%0,%1,%2,%3}, [%4];"
                 : "=r"(r[0]), "=r"(r[1]), "=r"(r[2]), "=r"(r[3]) : "r"(addr));
}
__device__ __forceinline__ void mma16816(float* d, const uint32_t* a, const uint32_t* b) {
    asm volatile(
        "mma.sync.aligned.m16n8k16.row.col.f32.f16.f16.f32 "
        "{%0,%1,%2,%3}, {%4,%5,%6,%7}, {%8,%9}, {%0,%1,%2,%3};"
        : "+f"(d[0]), "+f"(d[1]), "+f"(d[2]), "+f"(d[3])
        : "r"(a[0]), "r"(a[1]), "r"(a[2]), "r"(a[3]), "r"(b[0]), "r"(b[1]));
}
__device__ __forceinline__ uint32_t packh(float a, float b) {
    __half2 h = __floats2half2_rn(a, b);
    return *(uint32_t*)&h;
}

// ---------------------------------------------------------------------------
// NT tensor-core GEMM (mma.sync fp16, fp32 accum), NSEG K-segment products:
//   C[m,n] = sum_s A_s[m,:] . B_s[n,:]
// CTA tile 128x128, K chunks of 64, 3-stage cp.async pipeline.
// EPI 0: row sum-of-squares -> scpart[bx*MTOK + row]
// EPI 1: fp16 hi/lo split store (Ohi/Olo), leading dim ldo
// EPI 2: fp16 hi-only store (Ohi), leading dim ldo
// ---------------------------------------------------------------------------
#define STAGE 32768
#define SMEM_BYTES (3 * STAGE)

template <int EPI, int NSEG>
__global__ __launch_bounds__(256) void tc_gemm(
    const __half* __restrict__ A0, const __half* __restrict__ A1,
    const __half* __restrict__ A2,
    const __half* __restrict__ B0, const __half* __restrict__ B1,
    const __half* __restrict__ B2,
    int lda, int ldb, int Kseg,
    float* __restrict__ scpart,
    __half* __restrict__ Ohi, __half* __restrict__ Olo, int ldo)
{
    extern __shared__ __align__(1024) char dsm[];
    const uint32_t sbase = smem_u32(dsm);
    const int tid  = threadIdx.x;
    const int lane = tid & 31;
    const int wid  = tid >> 5;
    const int warp_m = wid & 1;
    const int warp_n = wid >> 1;
    const int m0 = blockIdx.y * 128;
    const int n0 = blockIdx.x * 128;

    const __half* Aarr[3] = {A0, A1, A2};
    const __half* Barr[3] = {B0, B1, B2};

    const int nch = Kseg >> 6;
    const int n   = NSEG * nch;

    float acc[4][4][4];
#pragma unroll
    for (int a = 0; a < 4; ++a)
#pragma unroll
        for (int b = 0; b < 4; ++b)
#pragma unroll
            for (int c = 0; c < 4; ++c) acc[a][b][c] = 0.f;

    auto load_chunk = [&](int j) {
        const int st  = j % 3;
        const int seg = j / nch;
        const int kc  = (j - seg * nch) << 6;
        const uint32_t sA = sbase + st * STAGE;
        const __half* As = Aarr[seg];
        const __half* Bs = Barr[seg];
#pragma unroll
        for (int i = 0; i < 4; ++i) {
            int id = i * 256 + tid;
            int row = id >> 3, ch = id & 7;
            cp16(sA + SWZ(row * 128 + ch * 16),
                 As + (size_t)(m0 + row) * lda + kc + ch * 8);
        }
#pragma unroll
        for (int i = 0; i < 4; ++i) {
            int id = i * 256 + tid;
            int row = id >> 3, ch = id & 7;
            cp16(sA + 16384 + SWZ(row * 128 + ch * 16),
                 Bs + (size_t)(n0 + row) * ldb + kc + ch * 8);
        }
    };

    const int arow = warp_m * 64 + (lane & 15);
    const int asel = lane >> 4;
    const int brow = warp_n * 32 + ((lane >> 4) << 3) + (lane & 7);
    const int bsel = (lane >> 3) & 1;

    load_chunk(0); CP_COMMIT();
    load_chunk(1); CP_COMMIT();

    for (int j = 0; j < n; ++j) {
        CP_WAIT1();
        __syncthreads();
        if (j + 2 < n) load_chunk(j + 2);
        CP_COMMIT();

        const uint32_t sA = sbase + (j % 3) * STAGE;
        const uint32_t sB = sA + 16384;
#pragma unroll
        for (int ks = 0; ks < 4; ++ks) {
            uint32_t afr[4][4], bfr[2][4];
#pragma unroll
            for (int mt = 0; mt < 4; ++mt)
                ldm_x4(afr[mt], sA + SWZ((arow + mt * 16) * 128 + (ks * 2 + asel) * 16));
#pragma unroll
            for (int p = 0; p < 2; ++p)
                ldm_x4(bfr[p], sB + SWZ((brow + p * 16) * 128 + (ks * 2 + bsel) * 16));
#pragma unroll
            for (int mt = 0; mt < 4; ++mt)
#pragma unroll
                for (int nt = 0; nt < 4; ++nt)
                    mma16816(acc[mt][nt], afr[mt], &bfr[nt >> 1][(nt & 1) * 2]);
        }
    }
    __syncthreads();

    const int rbase = warp_m * 64 + (lane >> 2);
    const int cbase = warp_n * 32 + (lane & 3) * 2;

    if (EPI == 0) {
        float* red = (float*)dsm;
#pragma unroll
        for (int mt = 0; mt < 4; ++mt) {
#pragma unroll
            for (int h = 0; h < 2; ++h) {
                float s = 0.f;
#pragma unroll
                for (int nt = 0; nt < 4; ++nt) {
                    float d0 = acc[mt][nt][2 * h], d1 = acc[mt][nt][2 * h + 1];
                    s = fmaf(d0, d0, fmaf(d1, d1, s));
                }
                s += __shfl_xor_sync(0xffffffffu, s, 1);
                s += __shfl_xor_sync(0xffffffffu, s, 2);
                if ((lane & 3) == 0)
                    red[warp_n * 128 + warp_m * 64 + mt * 16 + h * 8 + (lane >> 2)] = s;
            }
        }
        __syncthreads();
        if (tid < 128) {
            float s = red[tid] + red[128 + tid] + red[256 + tid] + red[384 + tid];
            scpart[(size_t)blockIdx.x * MTOK + m0 + tid] = s;
        }
    } else if (EPI == 1) {
#pragma unroll
        for (int mt = 0; mt < 4; ++mt)
#pragma unroll
            for (int h = 0; h < 2; ++h) {
                int row = m0 + rbase + mt * 16 + h * 8;
#pragma unroll
                for (int nt = 0; nt < 4; ++nt) {
                    float v0 = acc[mt][nt][2 * h], v1 = acc[mt][nt][2 * h + 1];
                    __half h0 = __float2half_rn(v0);
                    __half h1 = __float2half_rn(v1);
                    uint32_t hp = packh(v0, v1);
                    uint32_t lp = packh(v0 - __half2float(h0), v1 - __half2float(h1));
                    size_t off = (size_t)row * ldo + n0 + cbase + nt * 8;
                    *(uint32_t*)(Ohi + off) = hp;
                    *(uint32_t*)(Olo + off) = lp;
                }
            }
    } else {
#pragma unroll
        for (int mt = 0; mt < 4; ++mt)
#pragma unroll
            for (int h = 0; h < 2; ++h) {
                int row = m0 + rbase + mt * 16 + h * 8;
#pragma unroll
                for (int nt = 0; nt < 4; ++nt) {
                    uint32_t hp = packh(acc[mt][nt][2 * h], acc[mt][nt][2 * h + 1]);
                    *(uint32_t*)(Ohi + (size_t)row * ldo + n0 + cbase + nt * 8) = hp;
                }
            }
    }
}

// ---------------------------------------------------------------------------
// Attention GEMM: out[t,e] = (1/Z_t) * sum_{s<=t} P[t,s] u[s,e]
// P materialized as fp16 hi/lo (2-product). Chunk skipping via keep list:
// skip 64-wide s-chunk if stmin*(chunkmax - cmin) < -20 (provable bound).
// 3-stage cp.async pipeline over (Ph, Pl, uh) tiles.
// ---------------------------------------------------------------------------
#define AG_STAGE 49152                 // Ph 16K + Pl 16K + U 16K
#define AG_KEEP  (3 * AG_STAGE)        // keepList int[32]
#define AG_META  (AG_KEEP + 128)
#define AG_SMEM  (AG_META + 16)

__global__ __launch_bounds__(256) void attn_gemm(
    const __half* __restrict__ Ph, const __half* __restrict__ Pl,
    const __half* __restrict__ uh, float* __restrict__ out)
{
    extern __shared__ __align__(1024) char dsm[];
    const uint32_t sbase = smem_u32(dsm);
    int*  keepL = (int*)(dsm + AG_KEEP);
    int*  meta  = (int*)(dsm + AG_META);

    const int tid  = threadIdx.x;
    const int lane = tid & 31;
    const int wid  = tid >> 5;
    const int warp_m = wid & 1;
    const int warp_n = wid >> 1;
    const int m0 = blockIdx.y * 128;       // token tile (within batch)
    const int n0 = blockIdx.x * 128;       // e tile
    const int z  = blockIdx.z;

    // keep list (warp 0): conservative chunk skip
    if (wid == 0) {
        float v = fminf(fminf(g_sc[z * TSEQ + m0 + lane * 4],
                              g_sc[z * TSEQ + m0 + lane * 4 + 1]),
                        fminf(g_sc[z * TSEQ + m0 + lane * 4 + 2],
                              g_sc[z * TSEQ + m0 + lane * 4 + 3]));
#pragma unroll
        for (int o = 16; o; o >>= 1) v = fminf(v, __shfl_xor_sync(0xffffffffu, v, o));
        float stmin = v;
        float cmin = g_cmax[z * TSEQ + m0];
        int nch = (m0 + 128) >> 6;
        bool keep = false;
        if (lane < nch) {
            float chm = g_chunkmax[z * 32 + lane];
            keep = stmin * (chm - cmin) > -20.f;
        }
        uint32_t mask = __ballot_sync(0xffffffffu, keep);
        if (keep) keepL[__popc(mask & ((1u << lane) - 1))] = lane;
        if (lane == 0) meta[0] = __popc(mask);
    }
    __syncthreads();
    const int n = meta[0];

    float acc[4][4][4];
#pragma unroll
    for (int a = 0; a < 4; ++a)
#pragma unroll
        for (int b = 0; b < 4; ++b)
#pragma unroll
            for (int c = 0; c < 4; ++c) acc[a][b][c] = 0.f;

    auto load_chunk = [&](int j) {
        const int c = keepL[j];
        const uint32_t sA = sbase + (j % 3) * AG_STAGE;
#pragma unroll
        for (int i = 0; i < 4; ++i) {
            int id = i * 256 + tid;
            int row = id >> 3, ch = id & 7;
            uint32_t sw = SWZ(row * 128 + ch * 16);
            size_t poff = (size_t)(z * TSEQ + m0 + row) * TSEQ + c * 64 + ch * 8;
            cp16(sA + sw, Ph + poff);
            cp16(sA + 16384 + sw, Pl + poff);
            cp16(sA + 32768 + sw,
                 uh + (size_t)(n0 + row) * MTOK + z * TSEQ + c * 64 + ch * 8);
        }
    };

    const int arow = warp_m * 64 + (lane & 15);
    const int asel = lane >> 4;
    const int brow = warp_n * 32 + ((lane >> 4) << 3) + (lane & 7);
    const int bsel = (lane >> 3) & 1;

    load_chunk(0); CP_COMMIT();
    if (n > 1) load_chunk(1);
    CP_COMMIT();

    for (int j = 0; j < n; ++j) {
        CP_WAIT1();
        __syncthreads();
        if (j + 2 < n) load_chunk(j + 2);
        CP_COMMIT();

        const uint32_t sH = sbase + (j % 3) * AG_STAGE;
        const uint32_t sL = sH + 16384;
        const uint32_t sU = sH + 32768;
#pragma unroll
        for (int ks = 0; ks < 4; ++ks) {
            uint32_t ah[4][4], al[4][4], bfr[2][4];
#pragma unroll
            for (int mt = 0; mt < 4; ++mt) {
                uint32_t sw = SWZ((arow + mt * 16) * 128 + (ks * 2 + asel) * 16);
                ldm_x4(ah[mt], sH + sw);
                ldm_x4(al[mt], sL + sw);
            }
#pragma unroll
            for (int p = 0; p < 2; ++p)
                ldm_x4(bfr[p], sU + SWZ((brow + p * 16) * 128 + (ks * 2 + bsel) * 16));
#pragma unroll
            for (int mt = 0; mt < 4; ++mt)
#pragma unroll
                for (int nt = 0; nt < 4; ++nt) {
                    mma16816(acc[mt][nt], ah[mt], &bfr[nt >> 1][(nt & 1) * 2]);
                    mma16816(acc[mt][nt], al[mt], &bfr[nt >> 1][(nt & 1) * 2]);
                }
        }
    }

    const int rbase = warp_m * 64 + (lane >> 2);
    const int cbase = warp_n * 32 + (lane & 3) * 2;
#pragma unroll
    for (int mt = 0; mt < 4; ++mt)
#pragma unroll
        for (int h = 0; h < 2; ++h) {
            int rl = rbase + mt * 16 + h * 8;
            float scale = 1.f / g_Z[z * TSEQ + m0 + rl];
            float* Cp = out + (size_t)z * TSEQ * EDIM + (size_t)(m0 + rl) * EDIM + n0 + cbase;
#pragma unroll
            for (int nt = 0; nt < 4; ++nt) {
                float2 v = make_float2(acc[mt][nt][2 * h] * scale,
                                       acc[mt][nt][2 * h + 1] * scale);
                *(float2*)(Cp + nt * 8) = v;
            }
        }
}

// ---------------------------------------------------------------------------
// P generation (each exp computed exactly ONCE): fp16 hi/lo + exact row sums Z.
// Strict-upper region never written (device globals stay zero).
// ---------------------------------------------------------------------------
__global__ __launch_bounds__(256) void pgen_kernel()
{
    const int b = blockIdx.y;
    const int t0 = blockIdx.x * 32;
    const int warp = threadIdx.x >> 5, lane = threadIdx.x & 31;
    const float* scb = g_sc + b * TSEQ;
#pragma unroll
    for (int r = 0; r < 4; ++r) {
        const int t = t0 + warp * 4 + r;
        const float st = scb[t];
        const float m = st * g_cmax[b * TSEQ + t];
        float rowsum = 0.f;
        __half* Ph = g_Ph + ((size_t)(b * TSEQ + t)) * TSEQ;
        __half* Pl = g_Pl + ((size_t)(b * TSEQ + t)) * TSEQ;
        for (int sb = lane * 4; sb <= t; sb += 128) {
            float4 sv = *(const float4*)&scb[sb];
            float p0 = (sb + 0 <= t) ? __expf(fmaf(st, sv.x, -m)) : 0.f;
            float p1 = (sb + 1 <= t) ? __expf(fmaf(st, sv.y, -m)) : 0.f;
            float p2 = (sb + 2 <= t) ? __expf(fmaf(st, sv.z, -m)) : 0.f;
            float p3 = (sb + 3 <= t) ? __expf(fmaf(st, sv.w, -m)) : 0.f;
            rowsum += (p0 + p1) + (p2 + p3);
            __half h0 = __float2half_rn(p0), h1 = __float2half_rn(p1);
            __half h2 = __float2half_rn(p2), h3 = __float2half_rn(p3);
            *(uint32_t*)(Ph + sb)     = packh(p0, p1);
            *(uint32_t*)(Ph + sb + 2) = packh(p2, p3);
            *(uint32_t*)(Pl + sb)     = packh(p0 - __half2float(h0), p1 - __half2float(h1));
            *(uint32_t*)(Pl + sb + 2) = packh(p2 - __half2float(h2), p3 - __half2float(h3));
        }
#pragma unroll
        for (int o = 16; o; o >>= 1)
            rowsum += __shfl_xor_sync(0xffffffffu, rowsum, o);
        if (lane == 0) g_Z[b * TSEQ + t] = rowsum;
    }
}

// ---------------------------------------------------------------------------
// fp32 -> fp16 hi/lo split
// ---------------------------------------------------------------------------
__global__ __launch_bounds__(256) void split_kernel(
    const float* __restrict__ src, __half* __restrict__ hi,
    __half* __restrict__ lo, int nElem)
{
    int i = (blockIdx.x * 256 + threadIdx.x) * 4;
    if (i >= nElem) return;
    float4 v = *(const float4*)(src + i);
    __half h0 = __float2half_rn(v.x), h1 = __float2half_rn(v.y);
    __half h2 = __float2half_rn(v.z), h3 = __float2half_rn(v.w);
    *(uint32_t*)(hi + i)     = packh(v.x, v.y);
    *(uint32_t*)(hi + i + 2) = packh(v.z, v.w);
    *(uint32_t*)(lo + i)     = packh(v.x - __half2float(h0), v.y - __half2float(h1));
    *(uint32_t*)(lo + i + 2) = packh(v.z - __half2float(h2), v.w - __half2float(h3));
}

// transpose + split (1024 x 1024)
__global__ __launch_bounds__(256) void transpose_split_kernel(
    const float* __restrict__ src, __half* __restrict__ th, __half* __restrict__ tl)
{
    __shared__ float tile[32][33];
    int x = blockIdx.x * 32 + threadIdx.x;
    int y0 = blockIdx.y * 32 + threadIdx.y;
#pragma unroll
    for (int i = 0; i < 4; ++i)
        tile[threadIdx.y + i * 8][threadIdx.x] = src[(size_t)(y0 + i * 8) * EDIM + x];
    __syncthreads();
    int ox = blockIdx.y * 32 + threadIdx.x;
    int oy0 = blockIdx.x * 32 + threadIdx.y;
#pragma unroll
    for (int i = 0; i < 4; ++i) {
        float v = tile[threadIdx.x][threadIdx.y + i * 8];
        __half h = __float2half_rn(v);
        th[(size_t)(oy0 + i * 8) * EDIM + ox] = h;
        tl[(size_t)(oy0 + i * 8) * EDIM + ox] = __float2half_rn(v - __half2float(h));
    }
}

// ---------------------------------------------------------------------------
// per-batch scalar kernel: sc reduce, chunk maxes, inclusive cummax
// ---------------------------------------------------------------------------
__global__ __launch_bounds__(1024) void scalar_kernel()
{
    __shared__ float s[TSEQ];
    const int b = blockIdx.x, tid = threadIdx.x;
#pragma unroll
    for (int h = 0; h < 2; ++h) {
        int t = tid + h * 1024;
        float v = 0.f;
#pragma unroll
        for (int p = 0; p < 8; ++p) v += g_scpart[p * MTOK + b * TSEQ + t];
        v *= 0.03125f;
        s[t] = v;
        g_sc[b * TSEQ + t] = v;
    }
    __syncthreads();
    if (tid < 32) {
        float m = s[tid * 64];
        for (int i = 1; i < 64; ++i) m = fmaxf(m, s[tid * 64 + i]);
        g_chunkmax[b * 32 + tid] = m;
    }
    // inclusive max-scan
    for (int off = 1; off < TSEQ; off <<= 1) {
        float v0 = s[tid];
        if (tid >= off) v0 = fmaxf(v0, s[tid - off]);
        float v1 = fmaxf(s[tid + 1024], s[tid + 1024 - off]);
        __syncthreads();
        s[tid] = v0; s[tid + 1024] = v1;
        __syncthreads();
    }
    g_cmax[b * TSEQ + tid]        = s[tid];
    g_cmax[b * TSEQ + tid + 1024] = s[tid + 1024];
}

// ---------------------------------------------------------------------------
// launch
// ---------------------------------------------------------------------------
extern "C" void kernel_launch(void* const* d_in, const int* in_sizes, int n_in,
                              void* d_out, int out_size)
{
    const float* x   = (const float*)d_in[0];
    const float* wj  = (const float*)d_in[1];
    const float* wjv = (const float*)d_in[2];
    const float* wo  = (const float*)d_in[3];
    float* out = (float*)d_out;

    __half *xh, *xl, *wjh, *wjl, *woh, *wol, *wvth, *wvtl, *Wch, *Wcl, *uh, *Ph, *Pl;
    float *scpart;
    cudaGetSymbolAddress((void**)&xh, g_xh);   cudaGetSymbolAddress((void**)&xl, g_xl);
    cudaGetSymbolAddress((void**)&wjh, g_wjh); cudaGetSymbolAddress((void**)&wjl, g_wjl);
    cudaGetSymbolAddress((void**)&woh, g_woh); cudaGetSymbolAddress((void**)&wol, g_wol);
    cudaGetSymbolAddress((void**)&wvth, g_wvth); cudaGetSymbolAddress((void**)&wvtl, g_wvtl);
    cudaGetSymbolAddress((void**)&Wch, g_Wch); cudaGetSymbolAddress((void**)&Wcl, g_Wcl);
    cudaGetSymbolAddress((void**)&uh, g_uh);
    cudaGetSymbolAddress((void**)&Ph, g_Ph);   cudaGetSymbolAddress((void**)&Pl, g_Pl);
    cudaGetSymbolAddress((void**)&scpart, g_scpart);

    cudaFuncSetAttribute(tc_gemm<0, 3>, cudaFuncAttributeMaxDynamicSharedMemorySize, SMEM_BYTES);
    cudaFuncSetAttribute(tc_gemm<1, 3>, cudaFuncAttributeMaxDynamicSharedMemorySize, SMEM_BYTES);
    cudaFuncSetAttribute(tc_gemm<2, 2>, cudaFuncAttributeMaxDynamicSharedMemorySize, SMEM_BYTES);
    cudaFuncSetAttribute(attn_gemm, cudaFuncAttributeMaxDynamicSharedMemorySize, AG_SMEM);

    // 1. splits
    split_kernel<<<MTOK * EDIM / 1024, 256>>>(x, xh, xl, MTOK * EDIM);
    split_kernel<<<EDIM * EDIM / 1024, 256>>>(wj, wjh, wjl, EDIM * EDIM);
    split_kernel<<<EDIM * EDIM / 1024, 256>>>(wo, woh, wol, EDIM * EDIM);
    transpose_split_kernel<<<dim3(32, 32), dim3(32, 8)>>>(wjv, wvth, wvtl);

    // 2. sc partials: ||x@wj^T||^2  (hi*hi + hi*lo + lo*hi)
    tc_gemm<0, 3><<<dim3(8, 64), 256, SMEM_BYTES>>>(
        xh, xh, xl, wjh, wjl, wjh, EDIM, EDIM, EDIM,
        scpart, nullptr, nullptr, 0);
    scalar_kernel<<<BBATCH, 1024>>>();

    // 3. P materialized once (fp16 hi/lo) + exact Z
    pgen_kernel<<<dim3(TSEQ / 32, BBATCH), 256>>>();

    // 4. Wc = wo @ wjv  (hi*hi + hi*lo + lo*hi)
    tc_gemm<1, 3><<<dim3(8, 8), 256, SMEM_BYTES>>>(
        woh, woh, wol, wvth, wvtl, wvth, EDIM, EDIM, EDIM,
        nullptr, Wch, Wcl, EDIM);

    // 5. u^T = Wc @ x^T (2-product: (Wch+Wcl)·xh) -> hi only
    tc_gemm<2, 2><<<dim3(64, 8), 256, SMEM_BYTES>>>(
        Wch, Wcl, nullptr, xh, xh, nullptr, EDIM, EDIM, EDIM,
        nullptr, uh, nullptr, MTOK);

    // 6. attention GEMM: (P/Z) @ u with chunk skipping, 2-product P
    attn_gemm<<<dim3(8, 16, BBATCH), 256, AG_SMEM>>>(Ph, Pl, uh, out);
}

// round 13
// speedup vs baseline: 1.7336x; 1.2518x over previous
#include <cuda_runtime.h>
#include <cuda_fp16.h>
#include <stdint.h>
#include <math.h>

// Problem constants: B=4, T=2048, E=1024, H*D=1024
#define BBATCH 4
#define TSEQ   2048
#define EDIM   1024
#define MTOK   (BBATCH * TSEQ)

// ---------------------------------------------------------------------------
// Scratch (device globals, zero-initialized at module load)
// ---------------------------------------------------------------------------
__device__ __half g_xh [MTOK * EDIM];
__device__ __half g_xl [MTOK * EDIM];
__device__ __half g_wjh[EDIM * EDIM];
__device__ __half g_wjl[EDIM * EDIM];
__device__ __half g_woh[EDIM * EDIM];
__device__ __half g_wol[EDIM * EDIM];
__device__ __half g_wvth[EDIM * EDIM];
__device__ __half g_wvtl[EDIM * EDIM];
__device__ __half g_Wch[EDIM * EDIM];
__device__ __half g_uh [EDIM * MTOK];                    // u^T hi only
__device__ __half g_Ph [(size_t)BBATCH * TSEQ * TSEQ];   // P hi (16MB)
__device__ float g_scpart[8 * MTOK];
__device__ float g_sc  [MTOK];
__device__ float g_cmax[MTOK];
__device__ float g_Z   [MTOK];
__device__ float g_chunkmax[BBATCH * 32];

// ---------------------------------------------------------------------------
// helpers
// ---------------------------------------------------------------------------
__device__ __forceinline__ uint32_t smem_u32(const void* p) {
    uint32_t a;
    asm("{ .reg .u64 t; cvta.to.shared.u64 t, %1; cvt.u32.u64 %0, t; }"
        : "=r"(a) : "l"(p));
    return a;
}
__device__ __forceinline__ uint32_t SWZ(uint32_t x) { return x ^ ((x >> 3) & 0x70); }

__device__ __forceinline__ void cp16(uint32_t dst, const void* src) {
    asm volatile("cp.async.cg.shared.global [%0], [%1], 16;" :: "r"(dst), "l"(src) : "memory");
}
#define CP_COMMIT() asm volatile("cp.async.commit_group;" ::: "memory")
#define CP_WAIT1()  asm volatile("cp.async.wait_group 1;" ::: "memory")

__device__ __forceinline__ void ldm_x4(uint32_t* r, uint32_t addr) {
    asm volatile("ldmatrix.sync.aligned.m8n8.x4.shared.b16 {%0,%1,%2,%3}, [%4];"
                 : "=r"(r[0]), "=r"(r[1]), "=r"(r[2]), "=r"(r[3]) : "r"(addr));
}
__device__ __forceinline__ void mma16816(float* d, const uint32_t* a, const uint32_t* b) {
    asm volatile(
        "mma.sync.aligned.m16n8k16.row.col.f32.f16.f16.f32 "
        "{%0,%1,%2,%3}, {%4,%5,%6,%7}, {%8,%9}, {%0,%1,%2,%3};"
        : "+f"(d[0]), "+f"(d[1]), "+f"(d[2]), "+f"(d[3])
        : "r"(a[0]), "r"(a[1]), "r"(a[2]), "r"(a[3]), "r"(b[0]), "r"(b[1]));
}
__device__ __forceinline__ uint32_t packh(float a, float b) {
    __half2 h = __floats2half2_rn(a, b);
    return *(uint32_t*)&h;
}

// ---------------------------------------------------------------------------
// NT tensor-core GEMM (mma.sync fp16, fp32 accum), NSEG K-segment products:
//   C[m,n] = sum_s A_s[m,:] . B_s[n,:]
// CTA tile 128x128, K chunks of 64, 3-stage cp.async pipeline.
// EPI 0: row sum-of-squares -> scpart[bx*MTOK + row]
// EPI 2: fp16 hi-only store (Ohi), leading dim ldo
// ---------------------------------------------------------------------------
#define STAGE 32768
#define SMEM_BYTES (3 * STAGE)

template <int EPI, int NSEG>
__global__ __launch_bounds__(256) void tc_gemm(
    const __half* __restrict__ A0, const __half* __restrict__ A1,
    const __half* __restrict__ A2,
    const __half* __restrict__ B0, const __half* __restrict__ B1,
    const __half* __restrict__ B2,
    int lda, int ldb, int Kseg,
    float* __restrict__ scpart,
    __half* __restrict__ Ohi, int ldo)
{
    extern __shared__ __align__(1024) char dsm[];
    const uint32_t sbase = smem_u32(dsm);
    const int tid  = threadIdx.x;
    const int lane = tid & 31;
    const int wid  = tid >> 5;
    const int warp_m = wid & 1;
    const int warp_n = wid >> 1;
    const int m0 = blockIdx.y * 128;
    const int n0 = blockIdx.x * 128;

    const __half* Aarr[3] = {A0, A1, A2};
    const __half* Barr[3] = {B0, B1, B2};

    const int nch = Kseg >> 6;
    const int n   = NSEG * nch;

    float acc[4][4][4];
#pragma unroll
    for (int a = 0; a < 4; ++a)
#pragma unroll
        for (int b = 0; b < 4; ++b)
#pragma unroll
            for (int c = 0; c < 4; ++c) acc[a][b][c] = 0.f;

    auto load_chunk = [&](int j) {
        const int st  = j % 3;
        const int seg = j / nch;
        const int kc  = (j - seg * nch) << 6;
        const uint32_t sA = sbase + st * STAGE;
        const __half* As = Aarr[seg];
        const __half* Bs = Barr[seg];
#pragma unroll
        for (int i = 0; i < 4; ++i) {
            int id = i * 256 + tid;
            int row = id >> 3, ch = id & 7;
            cp16(sA + SWZ(row * 128 + ch * 16),
                 As + (size_t)(m0 + row) * lda + kc + ch * 8);
        }
#pragma unroll
        for (int i = 0; i < 4; ++i) {
            int id = i * 256 + tid;
            int row = id >> 3, ch = id & 7;
            cp16(sA + 16384 + SWZ(row * 128 + ch * 16),
                 Bs + (size_t)(n0 + row) * ldb + kc + ch * 8);
        }
    };

    const int arow = warp_m * 64 + (lane & 15);
    const int asel = lane >> 4;
    const int brow = warp_n * 32 + ((lane >> 4) << 3) + (lane & 7);
    const int bsel = (lane >> 3) & 1;

    load_chunk(0); CP_COMMIT();
    if (n > 1) load_chunk(1);
    CP_COMMIT();

    for (int j = 0; j < n; ++j) {
        CP_WAIT1();
        __syncthreads();
        if (j + 2 < n) load_chunk(j + 2);
        CP_COMMIT();

        const uint32_t sA = sbase + (j % 3) * STAGE;
        const uint32_t sB = sA + 16384;
#pragma unroll
        for (int ks = 0; ks < 4; ++ks) {
            uint32_t afr[4][4], bfr[2][4];
#pragma unroll
            for (int mt = 0; mt < 4; ++mt)
                ldm_x4(afr[mt], sA + SWZ((arow + mt * 16) * 128 + (ks * 2 + asel) * 16));
#pragma unroll
            for (int p = 0; p < 2; ++p)
                ldm_x4(bfr[p], sB + SWZ((brow + p * 16) * 128 + (ks * 2 + bsel) * 16));
#pragma unroll
            for (int mt = 0; mt < 4; ++mt)
#pragma unroll
                for (int nt = 0; nt < 4; ++nt)
                    mma16816(acc[mt][nt], afr[mt], &bfr[nt >> 1][(nt & 1) * 2]);
        }
    }
    __syncthreads();

    const int rbase = warp_m * 64 + (lane >> 2);
    const int cbase = warp_n * 32 + (lane & 3) * 2;

    if (EPI == 0) {
        float* red = (float*)dsm;
#pragma unroll
        for (int mt = 0; mt < 4; ++mt) {
#pragma unroll
            for (int h = 0; h < 2; ++h) {
                float s = 0.f;
#pragma unroll
                for (int nt = 0; nt < 4; ++nt) {
                    float d0 = acc[mt][nt][2 * h], d1 = acc[mt][nt][2 * h + 1];
                    s = fmaf(d0, d0, fmaf(d1, d1, s));
                }
                s += __shfl_xor_sync(0xffffffffu, s, 1);
                s += __shfl_xor_sync(0xffffffffu, s, 2);
                if ((lane & 3) == 0)
                    red[warp_n * 128 + warp_m * 64 + mt * 16 + h * 8 + (lane >> 2)] = s;
            }
        }
        __syncthreads();
        if (tid < 128) {
            float s = red[tid] + red[128 + tid] + red[256 + tid] + red[384 + tid];
            scpart[(size_t)blockIdx.x * MTOK + m0 + tid] = s;
        }
    } else {
#pragma unroll
        for (int mt = 0; mt < 4; ++mt)
#pragma unroll
            for (int h = 0; h < 2; ++h) {
                int row = m0 + rbase + mt * 16 + h * 8;
#pragma unroll
                for (int nt = 0; nt < 4; ++nt) {
                    uint32_t hp = packh(acc[mt][nt][2 * h], acc[mt][nt][2 * h + 1]);
                    *(uint32_t*)(Ohi + (size_t)row * ldo + n0 + cbase + nt * 8) = hp;
                }
            }
    }
}

// ---------------------------------------------------------------------------
// Attention GEMM: out[t,e] = (1/Z_t) * sum_{s<=t} P[t,s] u[s,e]
// P hi-only fp16 (quantization ~1.4e-4 rms, below u's fp16 floor).
// Chunk skipping via keep list: skip 64-wide s-chunk if
// stmin*(chunkmax - cmin) < -20 (provable bound).
// 3-stage cp.async pipeline over (Ph, uh) tiles.
// ---------------------------------------------------------------------------
#define AG_STAGE 32768                 // Ph 16K + U 16K
#define AG_KEEP  (3 * AG_STAGE)        // keepList int[32]
#define AG_META  (AG_KEEP + 128)
#define AG_SMEM  (AG_META + 16)

__global__ __launch_bounds__(256) void attn_gemm(
    const __half* __restrict__ Ph, const __half* __restrict__ uh,
    float* __restrict__ out)
{
    extern __shared__ __align__(1024) char dsm[];
    const uint32_t sbase = smem_u32(dsm);
    int*  keepL = (int*)(dsm + AG_KEEP);
    int*  meta  = (int*)(dsm + AG_META);

    const int tid  = threadIdx.x;
    const int lane = tid & 31;
    const int wid  = tid >> 5;
    const int warp_m = wid & 1;
    const int warp_n = wid >> 1;
    const int m0 = blockIdx.y * 128;       // token tile (within batch)
    const int n0 = blockIdx.x * 128;       // e tile
    const int z  = blockIdx.z;

    // keep list (warp 0): conservative chunk skip
    if (wid == 0) {
        float v = fminf(fminf(g_sc[z * TSEQ + m0 + lane * 4],
                              g_sc[z * TSEQ + m0 + lane * 4 + 1]),
                        fminf(g_sc[z * TSEQ + m0 + lane * 4 + 2],
                              g_sc[z * TSEQ + m0 + lane * 4 + 3]));
#pragma unroll
        for (int o = 16; o; o >>= 1) v = fminf(v, __shfl_xor_sync(0xffffffffu, v, o));
        float stmin = v;
        float cmin = g_cmax[z * TSEQ + m0];
        int nch = (m0 + 128) >> 6;
        bool keep = false;
        if (lane < nch) {
            float chm = g_chunkmax[z * 32 + lane];
            keep = stmin * (chm - cmin) > -20.f;
        }
        uint32_t mask = __ballot_sync(0xffffffffu, keep);
        if (keep) keepL[__popc(mask & ((1u << lane) - 1))] = lane;
        if (lane == 0) meta[0] = __popc(mask);
    }
    __syncthreads();
    const int n = meta[0];

    float acc[4][4][4];
#pragma unroll
    for (int a = 0; a < 4; ++a)
#pragma unroll
        for (int b = 0; b < 4; ++b)
#pragma unroll
            for (int c = 0; c < 4; ++c) acc[a][b][c] = 0.f;

    auto load_chunk = [&](int j) {
        const int c = keepL[j];
        const uint32_t sA = sbase + (j % 3) * AG_STAGE;
#pragma unroll
        for (int i = 0; i < 4; ++i) {
            int id = i * 256 + tid;
            int row = id >> 3, ch = id & 7;
            uint32_t sw = SWZ(row * 128 + ch * 16);
            cp16(sA + sw,
                 Ph + (size_t)(z * TSEQ + m0 + row) * TSEQ + c * 64 + ch * 8);
            cp16(sA + 16384 + sw,
                 uh + (size_t)(n0 + row) * MTOK + z * TSEQ + c * 64 + ch * 8);
        }
    };

    const int arow = warp_m * 64 + (lane & 15);
    const int asel = lane >> 4;
    const int brow = warp_n * 32 + ((lane >> 4) << 3) + (lane & 7);
    const int bsel = (lane >> 3) & 1;

    load_chunk(0); CP_COMMIT();
    if (n > 1) load_chunk(1);
    CP_COMMIT();

    for (int j = 0; j < n; ++j) {
        CP_WAIT1();
        __syncthreads();
        if (j + 2 < n) load_chunk(j + 2);
        CP_COMMIT();

        const uint32_t sH = sbase + (j % 3) * AG_STAGE;
        const uint32_t sU = sH + 16384;
#pragma unroll
        for (int ks = 0; ks < 4; ++ks) {
            uint32_t ah[4][4], bfr[2][4];
#pragma unroll
            for (int mt = 0; mt < 4; ++mt)
                ldm_x4(ah[mt], sH + SWZ((arow + mt * 16) * 128 + (ks * 2 + asel) * 16));
#pragma unroll
            for (int p = 0; p < 2; ++p)
                ldm_x4(bfr[p], sU + SWZ((brow + p * 16) * 128 + (ks * 2 + bsel) * 16));
#pragma unroll
            for (int mt = 0; mt < 4; ++mt)
#pragma unroll
                for (int nt = 0; nt < 4; ++nt)
                    mma16816(acc[mt][nt], ah[mt], &bfr[nt >> 1][(nt & 1) * 2]);
        }
    }

    const int rbase = warp_m * 64 + (lane >> 2);
    const int cbase = warp_n * 32 + (lane & 3) * 2;
#pragma unroll
    for (int mt = 0; mt < 4; ++mt)
#pragma unroll
        for (int h = 0; h < 2; ++h) {
            int rl = rbase + mt * 16 + h * 8;
            float scale = 1.f / g_Z[z * TSEQ + m0 + rl];
            float* Cp = out + (size_t)z * TSEQ * EDIM + (size_t)(m0 + rl) * EDIM + n0 + cbase;
#pragma unroll
            for (int nt = 0; nt < 4; ++nt) {
                float2 v = make_float2(acc[mt][nt][2 * h] * scale,
                                       acc[mt][nt][2 * h + 1] * scale);
                *(float2*)(Cp + nt * 8) = v;
            }
        }
}

// ---------------------------------------------------------------------------
// P generation (each exp computed exactly ONCE): fp16 hi + exact row sums Z.
// Strict-upper region never written (device globals stay zero).
// ---------------------------------------------------------------------------
__global__ __launch_bounds__(256) void pgen_kernel()
{
    const int b = blockIdx.y;
    const int t0 = blockIdx.x * 32;
    const int warp = threadIdx.x >> 5, lane = threadIdx.x & 31;
    const float* scb = g_sc + b * TSEQ;
#pragma unroll
    for (int r = 0; r < 4; ++r) {
        const int t = t0 + warp * 4 + r;
        const float st = scb[t];
        const float m = st * g_cmax[b * TSEQ + t];
        float rowsum = 0.f;
        __half* Ph = g_Ph + ((size_t)(b * TSEQ + t)) * TSEQ;
        for (int sb = lane * 4; sb <= t; sb += 128) {
            float4 sv = *(const float4*)&scb[sb];
            float p0 = (sb + 0 <= t) ? __expf(fmaf(st, sv.x, -m)) : 0.f;
            float p1 = (sb + 1 <= t) ? __expf(fmaf(st, sv.y, -m)) : 0.f;
            float p2 = (sb + 2 <= t) ? __expf(fmaf(st, sv.z, -m)) : 0.f;
            float p3 = (sb + 3 <= t) ? __expf(fmaf(st, sv.w, -m)) : 0.f;
            rowsum += (p0 + p1) + (p2 + p3);
            *(uint32_t*)(Ph + sb)     = packh(p0, p1);
            *(uint32_t*)(Ph + sb + 2) = packh(p2, p3);
        }
#pragma unroll
        for (int o = 16; o; o >>= 1)
            rowsum += __shfl_xor_sync(0xffffffffu, rowsum, o);
        if (lane == 0) g_Z[b * TSEQ + t] = rowsum;
    }
}

// ---------------------------------------------------------------------------
// fp32 -> fp16 hi/lo split
// ---------------------------------------------------------------------------
__global__ __launch_bounds__(256) void split_kernel(
    const float* __restrict__ src, __half* __restrict__ hi,
    __half* __restrict__ lo, int nElem)
{
    int i = (blockIdx.x * 256 + threadIdx.x) * 4;
    if (i >= nElem) return;
    float4 v = *(const float4*)(src + i);
    __half h0 = __float2half_rn(v.x), h1 = __float2half_rn(v.y);
    __half h2 = __float2half_rn(v.z), h3 = __float2half_rn(v.w);
    *(uint32_t*)(hi + i)     = packh(v.x, v.y);
    *(uint32_t*)(hi + i + 2) = packh(v.z, v.w);
    *(uint32_t*)(lo + i)     = packh(v.x - __half2float(h0), v.y - __half2float(h1));
    *(uint32_t*)(lo + i + 2) = packh(v.z - __half2float(h2), v.w - __half2float(h3));
}

// transpose + split (1024 x 1024)
__global__ __launch_bounds__(256) void transpose_split_kernel(
    const float* __restrict__ src, __half* __restrict__ th, __half* __restrict__ tl)
{
    __shared__ float tile[32][33];
    int x = blockIdx.x * 32 + threadIdx.x;
    int y0 = blockIdx.y * 32 + threadIdx.y;
#pragma unroll
    for (int i = 0; i < 4; ++i)
        tile[threadIdx.y + i * 8][threadIdx.x] = src[(size_t)(y0 + i * 8) * EDIM + x];
    __syncthreads();
    int ox = blockIdx.y * 32 + threadIdx.x;
    int oy0 = blockIdx.x * 32 + threadIdx.y;
#pragma unroll
    for (int i = 0; i < 4; ++i) {
        float v = tile[threadIdx.x][threadIdx.y + i * 8];
        __half h = __float2half_rn(v);
        th[(size_t)(oy0 + i * 8) * EDIM + ox] = h;
        tl[(size_t)(oy0 + i * 8) * EDIM + ox] = __float2half_rn(v - __half2float(h));
    }
}

// ---------------------------------------------------------------------------
// per-batch scalar kernel: sc reduce, chunk maxes, inclusive cummax
// ---------------------------------------------------------------------------
__global__ __launch_bounds__(1024) void scalar_kernel()
{
    __shared__ float s[TSEQ];
    const int b = blockIdx.x, tid = threadIdx.x;
#pragma unroll
    for (int h = 0; h < 2; ++h) {
        int t = tid + h * 1024;
        float v = 0.f;
#pragma unroll
        for (int p = 0; p < 8; ++p) v += g_scpart[p * MTOK + b * TSEQ + t];
        v *= 0.03125f;
        s[t] = v;
        g_sc[b * TSEQ + t] = v;
    }
    __syncthreads();
    if (tid < 32) {
        float m = s[tid * 64];
        for (int i = 1; i < 64; ++i) m = fmaxf(m, s[tid * 64 + i]);
        g_chunkmax[b * 32 + tid] = m;
    }
    // inclusive max-scan
    for (int off = 1; off < TSEQ; off <<= 1) {
        float v0 = s[tid];
        if (tid >= off) v0 = fmaxf(v0, s[tid - off]);
        float v1 = fmaxf(s[tid + 1024], s[tid + 1024 - off]);
        __syncthreads();
        s[tid] = v0; s[tid + 1024] = v1;
        __syncthreads();
    }
    g_cmax[b * TSEQ + tid]        = s[tid];
    g_cmax[b * TSEQ + tid + 1024] = s[tid + 1024];
}

// ---------------------------------------------------------------------------
// launch
// ---------------------------------------------------------------------------
extern "C" void kernel_launch(void* const* d_in, const int* in_sizes, int n_in,
                              void* d_out, int out_size)
{
    const float* x   = (const float*)d_in[0];
    const float* wj  = (const float*)d_in[1];
    const float* wjv = (const float*)d_in[2];
    const float* wo  = (const float*)d_in[3];
    float* out = (float*)d_out;

    __half *xh, *xl, *wjh, *wjl, *woh, *wol, *wvth, *wvtl, *Wch, *uh, *Ph;
    float *scpart;
    cudaGetSymbolAddress((void**)&xh, g_xh);   cudaGetSymbolAddress((void**)&xl, g_xl);
    cudaGetSymbolAddress((void**)&wjh, g_wjh); cudaGetSymbolAddress((void**)&wjl, g_wjl);
    cudaGetSymbolAddress((void**)&woh, g_woh); cudaGetSymbolAddress((void**)&wol, g_wol);
    cudaGetSymbolAddress((void**)&wvth, g_wvth); cudaGetSymbolAddress((void**)&wvtl, g_wvtl);
    cudaGetSymbolAddress((void**)&Wch, g_Wch);
    cudaGetSymbolAddress((void**)&uh, g_uh);
    cudaGetSymbolAddress((void**)&Ph, g_Ph);
    cudaGetSymbolAddress((void**)&scpart, g_scpart);

    cudaFuncSetAttribute(tc_gemm<0, 3>, cudaFuncAttributeMaxDynamicSharedMemorySize, SMEM_BYTES);
    cudaFuncSetAttribute(tc_gemm<2, 3>, cudaFuncAttributeMaxDynamicSharedMemorySize, SMEM_BYTES);
    cudaFuncSetAttribute(tc_gemm<2, 1>, cudaFuncAttributeMaxDynamicSharedMemorySize, SMEM_BYTES);
    cudaFuncSetAttribute(attn_gemm, cudaFuncAttributeMaxDynamicSharedMemorySize, AG_SMEM);

    // 1. splits
    split_kernel<<<MTOK * EDIM / 1024, 256>>>(x, xh, xl, MTOK * EDIM);
    split_kernel<<<EDIM * EDIM / 1024, 256>>>(wj, wjh, wjl, EDIM * EDIM);
    split_kernel<<<EDIM * EDIM / 1024, 256>>>(wo, woh, wol, EDIM * EDIM);
    transpose_split_kernel<<<dim3(32, 32), dim3(32, 8)>>>(wjv, wvth, wvtl);

    // 2. sc partials: ||x@wj^T||^2  (hi*hi + hi*lo + lo*hi) — precision-critical
    tc_gemm<0, 3><<<dim3(8, 64), 256, SMEM_BYTES>>>(
        xh, xh, xl, wjh, wjl, wjh, EDIM, EDIM, EDIM,
        scpart, nullptr, 0);
    scalar_kernel<<<BBATCH, 1024>>>();

    // 3. P materialized once (fp16 hi) + exact Z
    pgen_kernel<<<dim3(TSEQ / 32, BBATCH), 256>>>();

    // 4. Wc = wo @ wjv  (hi*hi + hi*lo + lo*hi) -> hi-only store
    tc_gemm<2, 3><<<dim3(8, 8), 256, SMEM_BYTES>>>(
        woh, woh, wol, wvth, wvtl, wvth, EDIM, EDIM, EDIM,
        nullptr, Wch, EDIM);

    // 5. u^T = Wch @ xh^T (1-product; error below u's fp16 storage floor)
    tc_gemm<2, 1><<<dim3(64, 8), 256, SMEM_BYTES>>>(
        Wch, nullptr, nullptr, xh, nullptr, nullptr, EDIM, EDIM, EDIM,
        nullptr, uh, MTOK);

    // 6. attention GEMM: (P/Z) @ u with chunk skipping, 1-product P
    attn_gemm<<<dim3(8, 16, BBATCH), 256, AG_SMEM>>>(Ph, uh, out);
}